// round 8
// baseline (speedup 1.0000x reference)
#include <cuda_runtime.h>
#include <cstdint>

#define BN    32
#define CH    256
#define HH    56
#define WW    56
#define HW    (HH*WW)            // 3136
#define TOTAL (BN*CH*HW)         // 25690112
#define WELEMS (CH*CH*9)         // 589824

// -------- device scratch ----------------------------------------------------
__device__ float         g_pre[TOTAL];             // conv + residual (pre-BN)
__device__ unsigned char g_fx[(size_t)BN*HW*CH];   // sign(x) e4m3, channel-last
__device__ unsigned char g_wf8[9*CH*CH];           // sign(w) e4m3 [tap][n][ci]
__device__ float         g_meanval;
__device__ float         g_csum[CH];
__device__ float         g_csq[CH];
__device__ float         g_scale[CH];
__device__ float         g_bias[CH];

__device__ __forceinline__ unsigned char sgn_e4m3(float v) {
    return v > 0.f ? 0x38u : (v < 0.f ? 0xB8u : 0x00u);
}

// ---------------- P0: mean(|clip(w,-1,1)|) + zero channel accumulators -----
__global__ void k_meanval(const float* __restrict__ w) {
    __shared__ float red[1024];
    if (threadIdx.x < CH) { g_csum[threadIdx.x] = 0.f; g_csq[threadIdx.x] = 0.f; }
    float s = 0.f;
    for (int i = threadIdx.x; i < WELEMS; i += 1024) {
        float v = fabsf(w[i]);
        s += (v < 1.f) ? v : 1.f;
    }
    red[threadIdx.x] = s;
    __syncthreads();
    for (int o = 512; o > 0; o >>= 1) {
        if (threadIdx.x < o) red[threadIdx.x] += red[threadIdx.x + o];
        __syncthreads();
    }
    if (threadIdx.x == 0) g_meanval = red[0] / (float)WELEMS;
}

// ---------------- P1: sign(w) -> e4m3 bytes [tap][n][ci] -------------------
__global__ void k_packw(const float* __restrict__ w) {
    int idx = blockIdx.x * 256 + threadIdx.x;
    if (idx >= 9 * CH * CH) return;
    int ci  = idx & 255;
    int n   = (idx >> 8) & 255;
    int tap = idx >> 16;
    g_wf8[idx] = sgn_e4m3(w[(n * CH + ci) * 9 + tap]);
}

// ---------------- P2: sign(x) -> channel-last e4m3 bytes -------------------
#define XP 260
__global__ void k_packx(const float* __restrict__ x) {
    __shared__ unsigned char tile[WW * XP];
    int b = blockIdx.x / HH, h = blockIdx.x % HH;
    for (int i = threadIdx.x; i < CH * WW; i += 256) {
        int c = i / WW, w = i - c * WW;
        tile[w * XP + c] = sgn_e4m3(x[((b * CH + c) * HH + h) * WW + w]);
    }
    __syncthreads();
    unsigned* dst = (unsigned*)g_fx;
    for (int j = threadIdx.x; j < WW * 64; j += 256) {
        int w = j >> 6, q = j & 63;
        unsigned v = *(const unsigned*)&tile[w * XP + q * 4];
        dst[((size_t)(b * HH + h) * WW + w) * 64 + q] = v;
    }
}

// ---------------- conv helpers ---------------------------------------------
__device__ __forceinline__ void mmaf8(float* c, const unsigned* a, const unsigned* b) {
    asm volatile(
        "mma.sync.aligned.m16n8k32.row.col.f32.e4m3.e4m3.f32 "
        "{%0,%1,%2,%3}, {%4,%5,%6,%7}, {%8,%9}, {%0,%1,%2,%3};\n"
        : "+f"(c[0]), "+f"(c[1]), "+f"(c[2]), "+f"(c[3])
        : "r"(a[0]), "r"(a[1]), "r"(a[2]), "r"(a[3]), "r"(b[0]), "r"(b[1]));
}
__device__ __forceinline__ void ldmx4(unsigned* r, uint32_t saddr) {
    asm volatile("ldmatrix.sync.aligned.m8n8.x4.shared.b16 {%0,%1,%2,%3}, [%4];"
        : "=r"(r[0]), "=r"(r[1]), "=r"(r[2]), "=r"(r[3]) : "r"(saddr));
}
#define CP16(dst, src) asm volatile("cp.async.cg.shared.global [%0], [%1], 16;" :: "r"(dst), "l"(src))
#define CP_COMMIT()    asm volatile("cp.async.commit_group;")
#define CP_WAIT0()     asm volatile("cp.async.wait_group 0;")

// swizzled layouts: row pitch 256B; 16B-chunk index q stored at (q ^ (row&7))
#define ABYTES (180 * 256)                // 46080
#define BBUF   (128 * 256)                // 32768 per buffer
#define CONV_SMEM (ABYTES + 2 * BBUF)     // 111616

// CTA: 128 px (16h x 8w) x 128 cout; 16 warps = 2(m) x 8(n); warp 64px x 16co
__global__ __launch_bounds__(512, 2) void k_conv(const float* __restrict__ x) {
    extern __shared__ unsigned char smem[];
    const uint32_t sA = (uint32_t)__cvta_generic_to_shared(smem);
    const uint32_t sB[2] = { sA + ABYTES, sA + ABYTES + BBUF };

    const int tid = threadIdx.x;
    const int warp = tid >> 5, lane = tid & 31;
    const int grp = lane >> 2, tig = lane & 3;
    const int wm = warp >> 3, wn = warp & 7;
    const int tw = blockIdx.x, th = blockIdx.y;
    const int b = blockIdx.z >> 1, n0 = (blockIdx.z & 1) * 128;
    const int h0 = th * 16, w0 = tw * 8;

    // ---- stage A: full 256-ch neighborhood, 180 px (18h x 10w), swizzled
    {
        for (int j = tid; j < 180 * 16; j += 512) {
            int p = j >> 4, q = j & 15;
            int nh = h0 - 1 + p / 10;
            int nw = w0 - 1 + p % 10;
            uint4 v = make_uint4(0u, 0u, 0u, 0u);
            if (nh >= 0 && nh < HH && nw >= 0 && nw < WW)
                v = *(const uint4*)(g_fx + ((size_t)((b * HH + nh) * WW + nw)) * CH + q * 16);
            *(uint4*)(smem + p * 256 + ((q ^ (p & 7)) << 4)) = v;
        }
    }
    // ---- stage B for tap 0 via cp.async (swizzled)
    {
        const char* wsrc = (const char*)(g_wf8 + n0 * 256);
        for (int j = tid; j < 2048; j += 512) {
            int r = j >> 4, q = j & 15;
            CP16(sB[0] + (uint32_t)(r * 256 + ((q ^ (r & 7)) << 4)), wsrc + j * 16);
        }
        CP_COMMIT();
        CP_WAIT0();
    }
    __syncthreads();

    float acc[4][2][4];
#pragma unroll
    for (int i = 0; i < 4; i++)
#pragma unroll
        for (int j = 0; j < 2; j++)
#pragma unroll
            for (int e = 0; e < 4; e++) acc[i][j][e] = 0.f;

    // lane-address components
    const int lrow8 = (lane >> 3) & 1;          // A: +8 px rows (matrices 1,3)
    const int lcol  = lane & 7;                 // A: px col within 8
    const uint32_t lchalf = ((lane >> 4) << 4); // A: +16B (k bytes 16..31)
    const int pmrow = wm * 8;

    // B lane mapping: m=lane>>3 -> fn=m>>1, khalf=m&1; row bi=lane&7
    const int bm = lane >> 3, bi = lane & 7;
    const uint32_t lcB = (uint32_t)(((bm & 1) << 4) ^ (bi << 4));   // chunk xor const
    const uint32_t brow = (uint32_t)((wn * 16 + (bm >> 1) * 8 + bi) * 256);

    for (int tap = 0; tap < 9; tap++) {
        const int dh = tap / 3, dw = tap % 3;

        // prefetch next tap's B into the other buffer
        if (tap + 1 < 9) {
            const char* wsrc = (const char*)(g_wf8 + (tap + 1) * 65536 + n0 * 256);
            const uint32_t dstb = sB[(tap + 1) & 1];
            for (int j = tid; j < 2048; j += 512) {
                int r = j >> 4, q = j & 15;
                CP16(dstb + (uint32_t)(r * 256 + ((q ^ (r & 7)) << 4)), wsrc + j * 16);
            }
            CP_COMMIT();
        }
        const uint32_t bB = sB[tap & 1] + brow;

        // per-fm A row base + lane xor-const for this tap
        uint32_t apre[4], alc[4];
#pragma unroll
        for (int fm = 0; fm < 4; fm++) {
            int nbrow = (pmrow + fm * 2 + lrow8 + dh) * 10 + lcol + dw;
            apre[fm] = sA + (uint32_t)(nbrow << 8);
            alc[fm]  = lchalf ^ (uint32_t)((nbrow & 7) << 4);
        }

#pragma unroll
        for (int ks = 0; ks < 8; ks++) {
            const uint32_t k32 = (uint32_t)(ks << 5);
            unsigned bfr[4];
            ldmx4(bfr, bB + (k32 ^ lcB));
#pragma unroll
            for (int fm = 0; fm < 4; fm++) {
                unsigned afr[4];
                ldmx4(afr, apre[fm] + (k32 ^ alc[fm]));
                mmaf8(acc[fm][0], afr, &bfr[0]);
                mmaf8(acc[fm][1], afr, &bfr[2]);
            }
        }
        CP_WAIT0();
        __syncthreads();
    }

    // ---- epilogue: v = mv*acc + x -> g_pre; fused per-channel BN partials
    const float mv = g_meanval;
#pragma unroll
    for (int fn = 0; fn < 2; fn++) {
#pragma unroll
        for (int e1 = 0; e1 < 2; e1++) {
            const int co = n0 + wn * 16 + fn * 8 + tig * 2 + e1;
            float s = 0.f, q = 0.f;
#pragma unroll
            for (int fm = 0; fm < 4; fm++) {
#pragma unroll
                for (int e2 = 0; e2 < 2; e2++) {
                    int p = wm * 64 + fm * 16 + grp + e2 * 8;
                    int h = h0 + (p >> 3), w = w0 + (p & 7);
                    if (h < HH) {
                        int idx = ((b * CH + co) * HH + h) * WW + w;
                        float v = mv * acc[fm][fn][e2 * 2 + e1] + x[idx];
                        g_pre[idx] = v;
                        s += v;
                        q += v * v;
                    }
                }
            }
            s += __shfl_xor_sync(0xFFFFFFFFu, s, 4);
            q += __shfl_xor_sync(0xFFFFFFFFu, q, 4);
            s += __shfl_xor_sync(0xFFFFFFFFu, s, 8);
            q += __shfl_xor_sync(0xFFFFFFFFu, q, 8);
            s += __shfl_xor_sync(0xFFFFFFFFu, s, 16);
            q += __shfl_xor_sync(0xFFFFFFFFu, q, 16);
            if (grp == 0) {
                atomicAdd(&g_csum[co], s);
                atomicAdd(&g_csq[co], q);
            }
        }
    }
}

// ---------------- R: finalize BN scale/bias --------------------------------
__global__ void k_bnfin(const float* __restrict__ gamma, const float* __restrict__ beta) {
    int c = threadIdx.x;
    const float inv = 1.f / (float)(BN * HW);
    float mean = g_csum[c] * inv;
    float var  = g_csq[c] * inv - mean * mean;
    float sc = gamma[c] * rsqrtf(var + 1e-5f);
    g_scale[c] = sc;
    g_bias[c]  = beta[c] - mean * sc;
}

// ---------------- E: apply BN affine + ReLU --------------------------------
__global__ void k_finish(float4* __restrict__ out) {
    int i = blockIdx.x * 256 + threadIdx.x;
    int c = (i / (HW / 4)) % CH;
    float sc = g_scale[c], bi = g_bias[c];
    float4 v = ((const float4*)g_pre)[i];
    float4 r;
    r.x = fmaxf(v.x * sc + bi, 0.f);
    r.y = fmaxf(v.y * sc + bi, 0.f);
    r.z = fmaxf(v.z * sc + bi, 0.f);
    r.w = fmaxf(v.w * sc + bi, 0.f);
    out[i] = r;
}

// ---------------- launch ---------------------------------------------------
extern "C" void kernel_launch(void* const* d_in, const int* in_sizes, int n_in,
                              void* d_out, int out_size) {
    const float* x     = (const float*)d_in[0];
    const float* w     = (const float*)d_in[1];
    const float* gamma = (const float*)d_in[2];
    const float* beta  = (const float*)d_in[3];

    cudaFuncSetAttribute(k_conv, cudaFuncAttributeMaxDynamicSharedMemorySize, CONV_SMEM);

    k_meanval<<<1, 1024>>>(w);
    k_packw<<<(9 * CH * CH + 255) / 256, 256>>>(w);
    k_packx<<<BN * HH, 256>>>(x);
    k_conv<<<dim3(7, 4, BN * 2), 512, CONV_SMEM>>>(x);
    k_bnfin<<<1, CH>>>(gamma, beta);
    k_finish<<<TOTAL / 4 / 256, 256>>>((float4*)d_out);
}

// round 9
// speedup vs baseline: 1.0824x; 1.0824x over previous
#include <cuda_runtime.h>
#include <cstdint>

#define BN    32
#define CH    256
#define HH    56
#define WW    56
#define HW    (HH*WW)            // 3136
#define TOTAL (BN*CH*HW)         // 25690112
#define WELEMS (CH*CH*9)         // 589824

// -------- device scratch ----------------------------------------------------
__device__ float         g_pre[TOTAL];             // conv + residual (pre-BN)
__device__ unsigned char g_fx[(size_t)BN*HW*CH];   // sign(x) e4m3, channel-last
__device__ unsigned char g_wf8[9*CH*CH];           // sign(w) e4m3 [tap][n][ci]
__device__ float         g_meanval;
__device__ float         g_csum[CH];
__device__ float         g_csq[CH];
__device__ float         g_scale[CH];
__device__ float         g_bias[CH];

__device__ __forceinline__ unsigned char sgn_e4m3(float v) {
    return v > 0.f ? 0x38u : (v < 0.f ? 0xB8u : 0x00u);
}

// ---------------- P0: mean(|clip(w,-1,1)|) + zero channel accumulators -----
__global__ void k_meanval(const float* __restrict__ w) {
    __shared__ float red[1024];
    if (threadIdx.x < CH) { g_csum[threadIdx.x] = 0.f; g_csq[threadIdx.x] = 0.f; }
    float s = 0.f;
    for (int i = threadIdx.x; i < WELEMS; i += 1024) {
        float v = fabsf(w[i]);
        s += (v < 1.f) ? v : 1.f;
    }
    red[threadIdx.x] = s;
    __syncthreads();
    for (int o = 512; o > 0; o >>= 1) {
        if (threadIdx.x < o) red[threadIdx.x] += red[threadIdx.x + o];
        __syncthreads();
    }
    if (threadIdx.x == 0) g_meanval = red[0] / (float)WELEMS;
}

// ---------------- P1: sign(w) -> e4m3 bytes [tap][n][ci] -------------------
__global__ void k_packw(const float* __restrict__ w) {
    int idx = blockIdx.x * 256 + threadIdx.x;
    if (idx >= 9 * CH * CH) return;
    int ci  = idx & 255;
    int n   = (idx >> 8) & 255;
    int tap = idx >> 16;
    g_wf8[idx] = sgn_e4m3(w[(n * CH + ci) * 9 + tap]);
}

// ---------------- P2: sign(x) -> channel-last e4m3 bytes -------------------
#define XP 260
__global__ void k_packx(const float* __restrict__ x) {
    __shared__ unsigned char tile[WW * XP];
    int b = blockIdx.x / HH, h = blockIdx.x % HH;
    for (int i = threadIdx.x; i < CH * WW; i += 256) {
        int c = i / WW, w = i - c * WW;
        tile[w * XP + c] = sgn_e4m3(x[((b * CH + c) * HH + h) * WW + w]);
    }
    __syncthreads();
    unsigned* dst = (unsigned*)g_fx;
    for (int j = threadIdx.x; j < WW * 64; j += 256) {
        int w = j >> 6, q = j & 63;
        unsigned v = *(const unsigned*)&tile[w * XP + q * 4];
        dst[((size_t)(b * HH + h) * WW + w) * 64 + q] = v;
    }
}

// ---------------- conv helpers ---------------------------------------------
__device__ __forceinline__ void mmaf8(float* c, const unsigned* a, const unsigned* b) {
    asm volatile(
        "mma.sync.aligned.m16n8k32.row.col.f32.e4m3.e4m3.f32 "
        "{%0,%1,%2,%3}, {%4,%5,%6,%7}, {%8,%9}, {%0,%1,%2,%3};\n"
        : "+f"(c[0]), "+f"(c[1]), "+f"(c[2]), "+f"(c[3])
        : "r"(a[0]), "r"(a[1]), "r"(a[2]), "r"(a[3]), "r"(b[0]), "r"(b[1]));
}
__device__ __forceinline__ void ldmx4(unsigned* r, uint32_t saddr) {
    asm volatile("ldmatrix.sync.aligned.m8n8.x4.shared.b16 {%0,%1,%2,%3}, [%4];"
        : "=r"(r[0]), "=r"(r[1]), "=r"(r[2]), "=r"(r[3]) : "r"(saddr));
}
#define CP16(dst, src) asm volatile("cp.async.cg.shared.global [%0], [%1], 16;" :: "r"(dst), "l"(src))
#define CP_COMMIT()    asm volatile("cp.async.commit_group;")
#define CP_WAIT0()     asm volatile("cp.async.wait_group 0;")

#define APITCH 272                        // A row: 256B data + 16B pad
#define ABYTES (180 * APITCH)             // 48960
#define BPITCH 272                        // B row: 256B data + 16B pad
#define BBUF   (256 * BPITCH)             // 69632 per buffer
#define CONV_SMEM (ABYTES + 2 * BBUF)     // 188224

// Block: 128 px (16h x 8w) x 256 cout; 16 warps = 2(m) x 8(n); warp 64px x 32co
__global__ __launch_bounds__(512, 1) void k_conv(const float* __restrict__ x) {
    extern __shared__ unsigned char smem[];
    const uint32_t sA = (uint32_t)__cvta_generic_to_shared(smem);
    const uint32_t sB[2] = { sA + ABYTES, sA + ABYTES + BBUF };

    const int tid = threadIdx.x;
    const int warp = tid >> 5, lane = tid & 31;
    const int grp = lane >> 2, tig = lane & 3;
    const int wm = warp >> 3, wn = warp & 7;
    const int tw = blockIdx.x, th = blockIdx.y, b = blockIdx.z;
    const int h0 = th * 16, w0 = tw * 8;

    // ---- stage A: full 256-ch neighborhood, 180 px (18h x 10w), zero-padded
    {
        for (int j = tid; j < 180 * 16; j += 512) {       // uint4 units
            int p = j >> 4, q = j & 15;
            int nh = h0 - 1 + p / 10;
            int nw = w0 - 1 + p % 10;
            uint4 v = make_uint4(0u, 0u, 0u, 0u);
            if (nh >= 0 && nh < HH && nw >= 0 && nw < WW)
                v = *(const uint4*)(g_fx + ((size_t)((b * HH + nh) * WW + nw)) * CH + q * 16);
            *(uint4*)(smem + p * APITCH + q * 16) = v;
        }
    }
    // ---- stage B for tap 0 via cp.async ([n] rows of 256B)
    {
        const char* wsrc = (const char*)g_wf8;
        for (int j = tid; j < 4096; j += 512) {           // uint4 units
            int r = j >> 4, q = j & 15;
            CP16(sB[0] + (uint32_t)(r * BPITCH + q * 16), wsrc + j * 16);
        }
        CP_COMMIT();
        CP_WAIT0();
    }
    __syncthreads();

    float acc[4][4][4];
#pragma unroll
    for (int i = 0; i < 4; i++)
#pragma unroll
        for (int j = 0; j < 4; j++)
#pragma unroll
            for (int e = 0; e < 4; e++) acc[i][j][e] = 0.f;

    // ldmatrix lane-address components
    const int lrow8 = (lane >> 3) & 1;    // A: +8 px rows for matrices 1,3
    const int lcol  = lane & 7;           // A: px col within 8
    const int lhalf = (lane >> 4) * 16;   // A: +16B (k bytes 16..31)
    const int pmrow = wm * 8;

    // B lane bases: m = lane>>3; n-group = half*2 + (m>>1); khalf = m&1
    const int bm = lane >> 3, bi = lane & 7;
    const int bkh = (bm & 1) * 16;
    uint32_t bbase[2][2];
#pragma unroll
    for (int bufi = 0; bufi < 2; bufi++)
#pragma unroll
        for (int half = 0; half < 2; half++)
            bbase[bufi][half] = sB[bufi] +
                (uint32_t)((wn * 32 + (half * 2 + (bm >> 1)) * 8 + bi) * BPITCH) + bkh;

    // register-double-buffered fragments (software pipeline over ks)
    unsigned afr[2][4][4];
    unsigned bfr[2][2][4];

    for (int tap = 0; tap < 9; tap++) {
        const int dh = tap / 3, dw = tap % 3;

        // prefetch next tap's B into the other buffer
        if (tap + 1 < 9) {
            const char* wsrc = (const char*)(g_wf8 + (tap + 1) * 65536);
            const uint32_t dstb = sB[(tap + 1) & 1];
            for (int j = tid; j < 4096; j += 512) {
                int r = j >> 4, q = j & 15;
                CP16(dstb + (uint32_t)(r * BPITCH + q * 16), wsrc + j * 16);
            }
            CP_COMMIT();
        }
        const int bufi = tap & 1;

        // per-fm A base addresses for this tap
        uint32_t abase[4];
#pragma unroll
        for (int fm = 0; fm < 4; fm++) {
            int nbrow = (pmrow + fm * 2 + lrow8 + dh) * 10 + lcol + dw;
            abase[fm] = sA + (uint32_t)(nbrow * APITCH) + lhalf;
        }

        // pipeline prologue: fragments for ks = 0
#pragma unroll
        for (int fm = 0; fm < 4; fm++)
            ldmx4(afr[0][fm], abase[fm]);
        ldmx4(bfr[0][0], bbase[bufi][0]);
        ldmx4(bfr[0][1], bbase[bufi][1]);

#pragma unroll
        for (int ks = 0; ks < 8; ks++) {              // 8 x k32 covers 256 ci
            const int cur = ks & 1, nxt = cur ^ 1;
            if (ks < 7) {                             // prefetch ks+1 fragments
#pragma unroll
                for (int fm = 0; fm < 4; fm++)
                    ldmx4(afr[nxt][fm], abase[fm] + (ks + 1) * 32);
                ldmx4(bfr[nxt][0], bbase[bufi][0] + (ks + 1) * 32);
                ldmx4(bfr[nxt][1], bbase[bufi][1] + (ks + 1) * 32);
            }
#pragma unroll
            for (int fm = 0; fm < 4; fm++)
#pragma unroll
                for (int fn = 0; fn < 4; fn++)
                    mmaf8(acc[fm][fn], afr[cur][fm], &bfr[cur][fn >> 1][(fn & 1) * 2]);
        }
        CP_WAIT0();
        __syncthreads();
    }

    // ---- epilogue: v = mv*acc + x -> g_pre; fused per-channel BN partials
    const float mv = g_meanval;
#pragma unroll
    for (int fn = 0; fn < 4; fn++) {
#pragma unroll
        for (int e1 = 0; e1 < 2; e1++) {
            const int co = wn * 32 + fn * 8 + tig * 2 + e1;
            float s = 0.f, q = 0.f;
#pragma unroll
            for (int fm = 0; fm < 4; fm++) {
#pragma unroll
                for (int e2 = 0; e2 < 2; e2++) {
                    int p = wm * 64 + fm * 16 + grp + e2 * 8;
                    int h = h0 + (p >> 3), w = w0 + (p & 7);
                    if (h < HH) {
                        int idx = ((b * CH + co) * HH + h) * WW + w;
                        float v = mv * acc[fm][fn][e2 * 2 + e1] + x[idx];
                        g_pre[idx] = v;
                        s += v;
                        q += v * v;
                    }
                }
            }
            s += __shfl_xor_sync(0xFFFFFFFFu, s, 4);
            q += __shfl_xor_sync(0xFFFFFFFFu, q, 4);
            s += __shfl_xor_sync(0xFFFFFFFFu, s, 8);
            q += __shfl_xor_sync(0xFFFFFFFFu, q, 8);
            s += __shfl_xor_sync(0xFFFFFFFFu, s, 16);
            q += __shfl_xor_sync(0xFFFFFFFFu, q, 16);
            if (grp == 0) {
                atomicAdd(&g_csum[co], s);
                atomicAdd(&g_csq[co], q);
            }
        }
    }
}

// ---------------- R: finalize BN scale/bias --------------------------------
__global__ void k_bnfin(const float* __restrict__ gamma, const float* __restrict__ beta) {
    int c = threadIdx.x;
    const float inv = 1.f / (float)(BN * HW);
    float mean = g_csum[c] * inv;
    float var  = g_csq[c] * inv - mean * mean;
    float sc = gamma[c] * rsqrtf(var + 1e-5f);
    g_scale[c] = sc;
    g_bias[c]  = beta[c] - mean * sc;
}

// ---------------- E: apply BN affine + ReLU --------------------------------
__global__ void k_finish(float4* __restrict__ out) {
    int i = blockIdx.x * 256 + threadIdx.x;
    int c = (i / (HW / 4)) % CH;
    float sc = g_scale[c], bi = g_bias[c];
    float4 v = ((const float4*)g_pre)[i];
    float4 r;
    r.x = fmaxf(v.x * sc + bi, 0.f);
    r.y = fmaxf(v.y * sc + bi, 0.f);
    r.z = fmaxf(v.z * sc + bi, 0.f);
    r.w = fmaxf(v.w * sc + bi, 0.f);
    out[i] = r;
}

// ---------------- launch ---------------------------------------------------
extern "C" void kernel_launch(void* const* d_in, const int* in_sizes, int n_in,
                              void* d_out, int out_size) {
    const float* x     = (const float*)d_in[0];
    const float* w     = (const float*)d_in[1];
    const float* gamma = (const float*)d_in[2];
    const float* beta  = (const float*)d_in[3];

    cudaFuncSetAttribute(k_conv, cudaFuncAttributeMaxDynamicSharedMemorySize, CONV_SMEM);

    k_meanval<<<1, 1024>>>(w);
    k_packw<<<(9 * CH * CH + 255) / 256, 256>>>(w);
    k_packx<<<BN * HH, 256>>>(x);
    k_conv<<<dim3(7, 4, BN), 512, CONV_SMEM>>>(x);
    k_bnfin<<<1, CH>>>(gamma, beta);
    k_finish<<<TOTAL / 4 / 256, 256>>>((float4*)d_out);
}